// round 3
// baseline (speedup 1.0000x reference)
#include <cuda_runtime.h>
#include <cstdint>

#define NW 8192
#define WW 512
#define PW 64

// ------------- device scratch (static, no allocation) -------------
__device__ float g_q[NW * PW];
__device__ float g_k[NW * PW];
__device__ float g_v[NW * PW];
__device__ float g_head[NW * PW];
__device__ float g_wsum[PW * WW];

// ------------- helpers -------------
__device__ __forceinline__ uint32_t f2tf(float f) {
    uint32_t o;
    asm volatile("cvt.rna.tf32.f32 %0, %1;" : "=r"(o) : "f"(f));
    return o;
}

__device__ __forceinline__ void mma8(float d[4],
                                     uint32_t a0, uint32_t a1, uint32_t a2, uint32_t a3,
                                     uint32_t b0, uint32_t b1) {
    asm("mma.sync.aligned.m16n8k8.row.col.f32.tf32.tf32.f32 "
        "{%0,%1,%2,%3},{%4,%5,%6,%7},{%8,%9},{%0,%1,%2,%3};"
        : "+f"(d[0]), "+f"(d[1]), "+f"(d[2]), "+f"(d[3])
        : "r"(a0), "r"(a1), "r"(a2), "r"(a3), "r"(b0), "r"(b1));
}

// ------------- kernel 1: q/k/v = x @ w_{q,k,v}  (fp32 FFMA) -------------
__global__ __launch_bounds__(256) void qkv_kernel(const float* __restrict__ x,
                                                  const float* __restrict__ wq,
                                                  const float* __restrict__ wk,
                                                  const float* __restrict__ wv) {
    __shared__ float xs[64][36];   // 64 rows x 32 cols (+4 pad)
    __shared__ float ws[32][68];   // 32 rows x 64 cols (+4 pad)

    const float* w = (blockIdx.y == 0) ? wq : (blockIdx.y == 1 ? wk : wv);
    float* out = (blockIdx.y == 0) ? g_q : (blockIdx.y == 1 ? g_k : g_v);

    int row0 = blockIdx.x * 64;
    int tid = threadIdx.x;
    int ty = tid >> 4, tx = tid & 15;

    float acc[4][4] = {};

    for (int kc = 0; kc < WW; kc += 32) {
        // stage x tile 64x32 (512 float4)
        #pragma unroll
        for (int i = 0; i < 2; i++) {
            int idx = tid + i * 256;
            int r = idx >> 3, c4 = (idx & 7) * 4;
            float4 v = *reinterpret_cast<const float4*>(&x[(row0 + r) * WW + kc + c4]);
            *reinterpret_cast<float4*>(&xs[r][c4]) = v;
        }
        // stage w tile 32x64 (512 float4)
        #pragma unroll
        for (int i = 0; i < 2; i++) {
            int idx = tid + i * 256;
            int r = idx >> 4, c4 = (idx & 15) * 4;
            float4 v = *reinterpret_cast<const float4*>(&w[(kc + r) * PW + c4]);
            *reinterpret_cast<float4*>(&ws[r][c4]) = v;
        }
        __syncthreads();

        #pragma unroll
        for (int k = 0; k < 32; k++) {
            float a[4];
            #pragma unroll
            for (int i = 0; i < 4; i++) a[i] = xs[ty * 4 + i][k];
            float4 b = *reinterpret_cast<float4*>(&ws[k][tx * 4]);
            #pragma unroll
            for (int i = 0; i < 4; i++) {
                acc[i][0] += a[i] * b.x;
                acc[i][1] += a[i] * b.y;
                acc[i][2] += a[i] * b.z;
                acc[i][3] += a[i] * b.w;
            }
        }
        __syncthreads();
    }

    #pragma unroll
    for (int i = 0; i < 4; i++)
        #pragma unroll
        for (int j = 0; j < 4; j++)
            out[(row0 + ty * 4 + i) * PW + tx * 4 + j] = acc[i][j];
}

// ------------- kernel 2: W_sum[i][j] = sum_h w_o[h*64+i][j] -------------
__global__ __launch_bounds__(256) void wsum_kernel(const float* __restrict__ wo) {
    int idx = blockIdx.x * 256 + threadIdx.x;   // 64*512 = 32768 total
    int i = idx >> 9, j = idx & 511;
    float s = 0.f;
    #pragma unroll
    for (int h = 0; h < 8; h++) s += wo[(h * 64 + i) * WW + j];
    g_wsum[i * WW + j] = s;
}

// ------------- kernel 3: fused attention (tf32 mma, no-max softmax) -------------
#define QS_LD 68
#define KS_LD 68
#define VS_LD 72
#define PS_LD 132
#define SMEM_ATTN_BYTES ((64 * QS_LD + 128 * KS_LD + 128 * VS_LD + 64 * PS_LD) * 4 + 128 * 4)

__global__ __launch_bounds__(256) void attn_kernel() {
    extern __shared__ uint32_t sm[];
    uint32_t* Qs = sm;                      // 64 x QS_LD (tf32 bits)
    uint32_t* Ks = Qs + 64 * QS_LD;         // 128 x KS_LD
    uint32_t* Vs = Ks + 128 * KS_LD;        // 128 x VS_LD
    uint32_t* Ps = Vs + 128 * VS_LD;        // 64 x PS_LD
    float* rspart = reinterpret_cast<float*>(Ps + 64 * PS_LD);  // [2][64]

    int tid = threadIdx.x;
    int warp = tid >> 5, lane = tid & 31;
    int r = lane >> 2, t = lane & 3;
    int wm = warp & 3, wn = warp >> 2;
    int m0 = wm * 16;       // warp row base within 64-row block
    int n0s = wn * 64;      // S-phase: warp covers cols n0s..n0s+63 of BN=128
    int oc0 = wn * 32;      // PV-phase: warp covers O cols oc0..oc0+31
    int qrow0 = blockIdx.x * 64;

    // stage Q block 64x64 -> tf32
    #pragma unroll
    for (int i = 0; i < 4; i++) {
        int idx = tid + i * 256;
        int rr = idx >> 4, c4 = (idx & 15) * 4;
        float4 v = *reinterpret_cast<const float4*>(&g_q[(qrow0 + rr) * PW + c4]);
        uint4 u = make_uint4(f2tf(v.x), f2tf(v.y), f2tf(v.z), f2tf(v.w));
        *reinterpret_cast<uint4*>(&Qs[rr * QS_LD + c4]) = u;
    }

    float oacc[4][4] = {};
    float rs0 = 0.f, rs1 = 0.f;
    const float cexp = 0.125f * 1.4426950408889634f;   // (1/sqrt(64)) * log2(e)

    for (int kb = 0; kb < 64; kb++) {
        int kr0 = kb * 128;
        // stage K tile 128x64 and V tile 128x64 -> tf32
        #pragma unroll
        for (int i = 0; i < 8; i++) {
            int idx = tid + i * 256;
            int rr = idx >> 4, c4 = (idx & 15) * 4;
            float4 v = *reinterpret_cast<const float4*>(&g_k[(kr0 + rr) * PW + c4]);
            uint4 u = make_uint4(f2tf(v.x), f2tf(v.y), f2tf(v.z), f2tf(v.w));
            *reinterpret_cast<uint4*>(&Ks[rr * KS_LD + c4]) = u;
        }
        #pragma unroll
        for (int i = 0; i < 8; i++) {
            int idx = tid + i * 256;
            int rr = idx >> 4, c4 = (idx & 15) * 4;
            float4 v = *reinterpret_cast<const float4*>(&g_v[(kr0 + rr) * PW + c4]);
            uint4 u = make_uint4(f2tf(v.x), f2tf(v.y), f2tf(v.z), f2tf(v.w));
            *reinterpret_cast<uint4*>(&Vs[rr * VS_LD + c4]) = u;
        }
        __syncthreads();

        // ---- S = Q K^T  (warp tile 16x64) ----
        float sacc[8][4] = {};
        #pragma unroll
        for (int kk = 0; kk < 8; kk++) {
            int k0 = kk * 8;
            uint32_t a0 = Qs[(m0 + r) * QS_LD + k0 + t];
            uint32_t a1 = Qs[(m0 + r + 8) * QS_LD + k0 + t];
            uint32_t a2 = Qs[(m0 + r) * QS_LD + k0 + t + 4];
            uint32_t a3 = Qs[(m0 + r + 8) * QS_LD + k0 + t + 4];
            #pragma unroll
            for (int j = 0; j < 8; j++) {
                int n = n0s + j * 8;
                uint32_t b0 = Ks[(n + r) * KS_LD + k0 + t];
                uint32_t b1 = Ks[(n + r) * KS_LD + k0 + t + 4];
                mma8(sacc[j], a0, a1, a2, a3, b0, b1);
            }
        }

        // ---- P = exp(S/8); rowsum partials; store P as tf32 ----
        #pragma unroll
        for (int j = 0; j < 8; j++) {
            float p0 = exp2f(sacc[j][0] * cexp);
            float p1 = exp2f(sacc[j][1] * cexp);
            float p2 = exp2f(sacc[j][2] * cexp);
            float p3 = exp2f(sacc[j][3] * cexp);
            rs0 += p0 + p1;
            rs1 += p2 + p3;
            int col = n0s + j * 8 + 2 * t;
            uint2 u01 = make_uint2(f2tf(p0), f2tf(p1));
            uint2 u23 = make_uint2(f2tf(p2), f2tf(p3));
            *reinterpret_cast<uint2*>(&Ps[(m0 + r) * PS_LD + col]) = u01;
            *reinterpret_cast<uint2*>(&Ps[(m0 + r + 8) * PS_LD + col]) = u23;
        }
        __syncthreads();

        // ---- O += P V  (warp tile 16x32) ----
        #pragma unroll
        for (int kk = 0; kk < 16; kk++) {
            int k0 = kk * 8;
            uint32_t a0 = Ps[(m0 + r) * PS_LD + k0 + t];
            uint32_t a1 = Ps[(m0 + r + 8) * PS_LD + k0 + t];
            uint32_t a2 = Ps[(m0 + r) * PS_LD + k0 + t + 4];
            uint32_t a3 = Ps[(m0 + r + 8) * PS_LD + k0 + t + 4];
            #pragma unroll
            for (int j = 0; j < 4; j++) {
                int n = oc0 + j * 8;
                uint32_t b0 = Vs[(k0 + t) * VS_LD + n + r];
                uint32_t b1 = Vs[(k0 + t + 4) * VS_LD + n + r];
                mma8(oacc[j], a0, a1, a2, a3, b0, b1);
            }
        }
        __syncthreads();
    }

    // ---- deterministic rowsum reduction ----
    rs0 += __shfl_xor_sync(0xffffffffu, rs0, 1);
    rs0 += __shfl_xor_sync(0xffffffffu, rs0, 2);
    rs1 += __shfl_xor_sync(0xffffffffu, rs1, 1);
    rs1 += __shfl_xor_sync(0xffffffffu, rs1, 2);
    if (t == 0) {
        rspart[wn * 64 + m0 + r] = rs0;
        rspart[wn * 64 + m0 + r + 8] = rs1;
    }
    __syncthreads();

    float inva = 1.0f / (rspart[m0 + r] + rspart[64 + m0 + r]);
    float invb = 1.0f / (rspart[m0 + r + 8] + rspart[64 + m0 + r + 8]);
    #pragma unroll
    for (int j = 0; j < 4; j++) {
        int col = oc0 + j * 8 + 2 * t;
        float2 ha = make_float2(oacc[j][0] * inva, oacc[j][1] * inva);
        float2 hb = make_float2(oacc[j][2] * invb, oacc[j][3] * invb);
        *reinterpret_cast<float2*>(&g_head[(qrow0 + m0 + r) * PW + col]) = ha;
        *reinterpret_cast<float2*>(&g_head[(qrow0 + m0 + r + 8) * PW + col]) = hb;
    }
}

// ------------- kernel 4: out = head @ W_sum  (fp32 FFMA) -------------
__global__ __launch_bounds__(256) void oproj_kernel(float* __restrict__ out) {
    __shared__ float hs[64][68];
    __shared__ float wss[64][68];

    int row0 = blockIdx.x * 64;
    int n0 = blockIdx.y * 64;
    int tid = threadIdx.x;

    #pragma unroll
    for (int i = 0; i < 4; i++) {
        int idx = tid + i * 256;
        int rr = idx >> 4, c4 = (idx & 15) * 4;
        *reinterpret_cast<float4*>(&hs[rr][c4]) =
            *reinterpret_cast<const float4*>(&g_head[(row0 + rr) * PW + c4]);
        *reinterpret_cast<float4*>(&wss[rr][c4]) =
            *reinterpret_cast<const float4*>(&g_wsum[rr * WW + n0 + c4]);
    }
    __syncthreads();

    int ty = tid >> 4, tx = tid & 15;
    float acc[4][4] = {};
    #pragma unroll
    for (int k = 0; k < 64; k++) {
        float a[4];
        #pragma unroll
        for (int i = 0; i < 4; i++) a[i] = hs[ty * 4 + i][k];
        float4 b = *reinterpret_cast<float4*>(&wss[k][tx * 4]);
        #pragma unroll
        for (int i = 0; i < 4; i++) {
            acc[i][0] += a[i] * b.x;
            acc[i][1] += a[i] * b.y;
            acc[i][2] += a[i] * b.z;
            acc[i][3] += a[i] * b.w;
        }
    }

    #pragma unroll
    for (int i = 0; i < 4; i++)
        #pragma unroll
        for (int j = 0; j < 4; j++)
            out[(row0 + ty * 4 + i) * WW + n0 + tx * 4 + j] = acc[i][j];
}

// ------------- launch -------------
extern "C" void kernel_launch(void* const* d_in, const int* in_sizes, int n_in,
                              void* d_out, int out_size) {
    const float* x  = (const float*)d_in[0];
    const float* wq = (const float*)d_in[1];
    const float* wk = (const float*)d_in[2];
    const float* wv = (const float*)d_in[3];
    const float* wo = (const float*)d_in[4];
    float* out = (float*)d_out;

    cudaFuncSetAttribute(attn_kernel, cudaFuncAttributeMaxDynamicSharedMemorySize,
                         SMEM_ATTN_BYTES);

    qkv_kernel<<<dim3(128, 3), 256>>>(x, wq, wk, wv);
    wsum_kernel<<<128, 256>>>(wo);
    attn_kernel<<<128, 256, SMEM_ATTN_BYTES>>>();
    oproj_kernel<<<dim3(128, 8), 256>>>(out);
}

// round 4
// speedup vs baseline: 1.8454x; 1.8454x over previous
#include <cuda_runtime.h>
#include <cuda_bf16.h>
#include <cstdint>

#define NW 8192
#define WW 512
#define PW 64
#define KP 72                 // smem tile pitch in bf16 elems
#define TILE_H (64 * KP)      // elems per 64x64 tile

// ------------- device scratch (static, no allocation) -------------
__device__ __align__(16) __nv_bfloat16 g_qb[NW * PW];
__device__ __align__(16) __nv_bfloat16 g_kb[NW * PW];
__device__ __align__(16) __nv_bfloat16 g_vhiT[PW * NW];   // [out_col][kv_row]
__device__ __align__(16) __nv_bfloat16 g_vloT[PW * NW];
__device__ __align__(16) float g_part[2 * NW * PW];
__device__ float g_esum[2 * NW];
__device__ float g_csv[PW];
__device__ __align__(16) float g_head[NW * PW];
__device__ __align__(16) float g_wsum[PW * WW];

// ------------- helpers -------------
__device__ __forceinline__ unsigned short bfb(__nv_bfloat16 b) {
    return reinterpret_cast<unsigned short&>(b);
}

__device__ __forceinline__ void mma16(float* d, const uint32_t* a, uint32_t b0, uint32_t b1) {
    asm volatile("mma.sync.aligned.m16n8k16.row.col.f32.bf16.bf16.f32 "
                 "{%0,%1,%2,%3},{%4,%5,%6,%7},{%8,%9},{%0,%1,%2,%3};"
                 : "+f"(d[0]), "+f"(d[1]), "+f"(d[2]), "+f"(d[3])
                 : "r"(a[0]), "r"(a[1]), "r"(a[2]), "r"(a[3]), "r"(b0), "r"(b1));
}

__device__ __forceinline__ void ldsm4(uint32_t& r0, uint32_t& r1, uint32_t& r2, uint32_t& r3,
                                      uint32_t addr) {
    asm volatile("ldmatrix.sync.aligned.m8n8.x4.shared.b16 {%0,%1,%2,%3},[%4];"
                 : "=r"(r0), "=r"(r1), "=r"(r2), "=r"(r3) : "r"(addr));
}

__device__ __forceinline__ float ex2(float x) {
    float r; asm("ex2.approx.f32 %0,%1;" : "=f"(r) : "f"(x)); return r;
}

// pack two fp32 -> bf16x2, lo in low half
__device__ __forceinline__ uint32_t pk2(float lo, float hi) {
    uint32_t r; asm("cvt.rn.bf16x2.f32 %0,%1,%2;" : "=r"(r) : "f"(hi), "f"(lo)); return r;
}

// ------------- kernel 1: q/k/v = x @ w  (fp32 FFMA, bf16 outputs) -------------
__global__ __launch_bounds__(256) void qkv_kernel(const float* __restrict__ x,
                                                  const float* __restrict__ wq,
                                                  const float* __restrict__ wk,
                                                  const float* __restrict__ wv) {
    __shared__ float xs[64][36];
    __shared__ float ws[32][68];

    const int which = blockIdx.y;
    const float* w = (which == 0) ? wq : (which == 1 ? wk : wv);

    int row0 = blockIdx.x * 64;
    int tid = threadIdx.x;
    int ty = tid >> 4, tx = tid & 15;

    float acc[4][4] = {};

    for (int kc = 0; kc < WW; kc += 32) {
        #pragma unroll
        for (int i = 0; i < 2; i++) {
            int idx = tid + i * 256;
            int r = idx >> 3, c4 = (idx & 7) * 4;
            *reinterpret_cast<float4*>(&xs[r][c4]) =
                *reinterpret_cast<const float4*>(&x[(row0 + r) * WW + kc + c4]);
        }
        #pragma unroll
        for (int i = 0; i < 2; i++) {
            int idx = tid + i * 256;
            int r = idx >> 4, c4 = (idx & 15) * 4;
            *reinterpret_cast<float4*>(&ws[r][c4]) =
                *reinterpret_cast<const float4*>(&w[(kc + r) * PW + c4]);
        }
        __syncthreads();

        #pragma unroll
        for (int k = 0; k < 32; k++) {
            float a[4];
            #pragma unroll
            for (int i = 0; i < 4; i++) a[i] = xs[ty * 4 + i][k];
            float4 b = *reinterpret_cast<float4*>(&ws[k][tx * 4]);
            #pragma unroll
            for (int i = 0; i < 4; i++) {
                acc[i][0] += a[i] * b.x;
                acc[i][1] += a[i] * b.y;
                acc[i][2] += a[i] * b.z;
                acc[i][3] += a[i] * b.w;
            }
        }
        __syncthreads();
    }

    if (which < 2) {
        __nv_bfloat16* out = (which == 0) ? g_qb : g_kb;
        #pragma unroll
        for (int i = 0; i < 4; i++) {
            ushort4 u;
            u.x = bfb(__float2bfloat16(acc[i][0]));
            u.y = bfb(__float2bfloat16(acc[i][1]));
            u.z = bfb(__float2bfloat16(acc[i][2]));
            u.w = bfb(__float2bfloat16(acc[i][3]));
            *reinterpret_cast<ushort4*>(&out[(row0 + ty * 4 + i) * PW + tx * 4]) = u;
        }
    } else {
        // V: split into hi/lo bf16, store TRANSPOSED [out_col][kv_row]
        #pragma unroll
        for (int j = 0; j < 4; j++) {
            ushort4 uh, ul;
            unsigned short* ph = &uh.x;
            unsigned short* pl = &ul.x;
            #pragma unroll
            for (int i = 0; i < 4; i++) {
                float a = acc[i][j];
                __nv_bfloat16 h = __float2bfloat16(a);
                __nv_bfloat16 l = __float2bfloat16(a - __bfloat162float(h));
                ph[i] = bfb(h);
                pl[i] = bfb(l);
            }
            int off = (tx * 4 + j) * NW + row0 + ty * 4;
            *reinterpret_cast<ushort4*>(&g_vhiT[off]) = uh;
            *reinterpret_cast<ushort4*>(&g_vloT[off]) = ul;
        }
    }
}

// ------------- kernel 2: W_sum[i][j] = sum_h w_o[h*64+i][j] -------------
__global__ __launch_bounds__(256) void wsum_kernel(const float* __restrict__ wo) {
    int idx = blockIdx.x * 256 + threadIdx.x;
    int i = idx >> 9, j = idx & 511;
    float s = 0.f;
    #pragma unroll
    for (int h = 0; h < 8; h++) s += wo[(h * 64 + i) * WW + j];
    g_wsum[i * WW + j] = s;
}

// ------------- kernel 2b: colsumV[j] = sum_i v[i][j] (from hi+lo) -------------
__global__ __launch_bounds__(256) void colsumv_kernel() {
    int j = blockIdx.x;
    const __nv_bfloat16* H = g_vhiT + j * NW;
    const __nv_bfloat16* L = g_vloT + j * NW;
    float s = 0.f;
    for (int i = threadIdx.x; i < NW; i += 256)
        s += __bfloat162float(H[i]) + __bfloat162float(L[i]);
    #pragma unroll
    for (int o = 16; o; o >>= 1) s += __shfl_xor_sync(0xffffffffu, s, o);
    __shared__ float red[8];
    if ((threadIdx.x & 31) == 0) red[threadIdx.x >> 5] = s;
    __syncthreads();
    if (threadIdx.x == 0) {
        float t = 0.f;
        #pragma unroll
        for (int w = 0; w < 8; w++) t += red[w];
        g_csv[j] = t;
    }
}

// ------------- kernel 3: fused attention (bf16 mma, p = 1+e trick) -------------
// grid (64, 2): 64 row-blocks of 128, 2 KV-splits of 4096. 256 threads = 8 warps x 16 rows.
#define SMEM_ATTN_BYTES (2 * 3 * TILE_H * 2)

__global__ __launch_bounds__(256, 1) void attn_kernel() {
    extern __shared__ __align__(16) uint16_t sm[];

    const int tid = threadIdx.x, warp = tid >> 5, lane = tid & 31;
    const int r = lane >> 2, t = lane & 3;
    const int m0 = warp * 16;
    const int qrow0 = blockIdx.x * 128;
    const int kvbase = blockIdx.y * 4096;

    // Q fragments, resident in registers for the whole kernel
    uint32_t aq[4][4];
    {
        const uint32_t* qb32 = reinterpret_cast<const uint32_t*>(g_qb);
        int ba = (qrow0 + m0 + r) * 32, bb = (qrow0 + m0 + r + 8) * 32;
        #pragma unroll
        for (int ks = 0; ks < 4; ks++) {
            aq[ks][0] = qb32[ba + ks * 8 + t];
            aq[ks][1] = qb32[bb + ks * 8 + t];
            aq[ks][2] = qb32[ba + ks * 8 + t + 4];
            aq[ks][3] = qb32[bb + ks * 8 + t + 4];
        }
    }

    const int srow = tid >> 3, schunk = tid & 7;
    const uint4* kb4 = reinterpret_cast<const uint4*>(g_kb);
    const uint4* vh4 = reinterpret_cast<const uint4*>(g_vhiT);
    const uint4* vl4 = reinterpret_cast<const uint4*>(g_vloT);

    const uint32_t smb = (uint32_t)__cvta_generic_to_shared(sm);
    const int nbase = ((lane >> 4) << 3) + (lane & 7);   // ldmatrix row-within
    const int koff = ((lane >> 3) & 1) * 8;              // ldmatrix k offset

    uint4 rk0, rk1, rh0, rh1, rl0, rl1;

    // prologue: load + stage tile 0 into buffer 0
    {
        int kr0 = kvbase;
        rk0 = kb4[(kr0 + srow) * 8 + schunk];
        rk1 = kb4[(kr0 + srow + 32) * 8 + schunk];
        rh0 = vh4[srow * (NW / 8) + (kr0 >> 3) + schunk];
        rh1 = vh4[(srow + 32) * (NW / 8) + (kr0 >> 3) + schunk];
        rl0 = vl4[srow * (NW / 8) + (kr0 >> 3) + schunk];
        rl1 = vl4[(srow + 32) * (NW / 8) + (kr0 >> 3) + schunk];
        uint16_t* b = sm;
        *reinterpret_cast<uint4*>(b + srow * KP + schunk * 8) = rk0;
        *reinterpret_cast<uint4*>(b + (srow + 32) * KP + schunk * 8) = rk1;
        *reinterpret_cast<uint4*>(b + TILE_H + srow * KP + schunk * 8) = rh0;
        *reinterpret_cast<uint4*>(b + TILE_H + (srow + 32) * KP + schunk * 8) = rh1;
        *reinterpret_cast<uint4*>(b + 2 * TILE_H + srow * KP + schunk * 8) = rl0;
        *reinterpret_cast<uint4*>(b + 2 * TILE_H + (srow + 32) * KP + schunk * 8) = rl1;
    }
    __syncthreads();

    float oacc[8][4] = {};
    float rs0 = 0.f, rs1 = 0.f;
    const float cexp = 0.18033688f;   // (1/8) * log2(e)

    for (int kb = 0; kb < 64; kb++) {
        // prefetch next tile into registers (overlaps with compute below)
        if (kb < 63) {
            int kr0 = kvbase + (kb + 1) * 64;
            rk0 = kb4[(kr0 + srow) * 8 + schunk];
            rk1 = kb4[(kr0 + srow + 32) * 8 + schunk];
            rh0 = vh4[srow * (NW / 8) + (kr0 >> 3) + schunk];
            rh1 = vh4[(srow + 32) * (NW / 8) + (kr0 >> 3) + schunk];
            rl0 = vl4[srow * (NW / 8) + (kr0 >> 3) + schunk];
            rl1 = vl4[(srow + 32) * (NW / 8) + (kr0 >> 3) + schunk];
        }

        uint32_t cb = smb + (uint32_t)((kb & 1) * 3 * TILE_H * 2);

        // ---- S = Q K^T  (warp: 16 x 64) ----
        float sacc[8][4] = {};
        #pragma unroll
        for (int ks = 0; ks < 4; ks++) {
            #pragma unroll
            for (int jp = 0; jp < 4; jp++) {
                uint32_t b0, b1, b2, b3;
                ldsm4(b0, b1, b2, b3, cb + 2u * ((jp * 16 + nbase) * KP + ks * 16 + koff));
                mma16(sacc[2 * jp], aq[ks], b0, b1);
                mma16(sacc[2 * jp + 1], aq[ks], b2, b3);
            }
        }

        // ---- e = exp(S/8) - 1; pack directly into PV A-fragments ----
        uint32_t ea[4][4];
        #pragma unroll
        for (int ks = 0; ks < 4; ks++) {
            float e00 = ex2(sacc[2 * ks][0] * cexp) - 1.f;
            float e01 = ex2(sacc[2 * ks][1] * cexp) - 1.f;
            float e02 = ex2(sacc[2 * ks][2] * cexp) - 1.f;
            float e03 = ex2(sacc[2 * ks][3] * cexp) - 1.f;
            float e10 = ex2(sacc[2 * ks + 1][0] * cexp) - 1.f;
            float e11 = ex2(sacc[2 * ks + 1][1] * cexp) - 1.f;
            float e12 = ex2(sacc[2 * ks + 1][2] * cexp) - 1.f;
            float e13 = ex2(sacc[2 * ks + 1][3] * cexp) - 1.f;
            rs0 += e00 + e01 + e10 + e11;
            rs1 += e02 + e03 + e12 + e13;
            ea[ks][0] = pk2(e00, e01);
            ea[ks][1] = pk2(e02, e03);
            ea[ks][2] = pk2(e10, e11);
            ea[ks][3] = pk2(e12, e13);
        }

        // ---- O += e * V_hi + e * V_lo  (warp: 16 x 64) ----
        uint32_t hb = cb + 2u * TILE_H, lb = cb + 4u * TILE_H;
        #pragma unroll
        for (int ks = 0; ks < 4; ks++) {
            #pragma unroll
            for (int jp = 0; jp < 4; jp++) {
                uint32_t off = 2u * ((jp * 16 + nbase) * KP + ks * 16 + koff);
                uint32_t b0, b1, b2, b3;
                ldsm4(b0, b1, b2, b3, hb + off);
                mma16(oacc[2 * jp], ea[ks], b0, b1);
                mma16(oacc[2 * jp + 1], ea[ks], b2, b3);
                ldsm4(b0, b1, b2, b3, lb + off);
                mma16(oacc[2 * jp], ea[ks], b0, b1);
                mma16(oacc[2 * jp + 1], ea[ks], b2, b3);
            }
        }

        // stage the prefetched tile into the other buffer
        if (kb < 63) {
            uint16_t* b = sm + ((kb + 1) & 1) * 3 * TILE_H;
            *reinterpret_cast<uint4*>(b + srow * KP + schunk * 8) = rk0;
            *reinterpret_cast<uint4*>(b + (srow + 32) * KP + schunk * 8) = rk1;
            *reinterpret_cast<uint4*>(b + TILE_H + srow * KP + schunk * 8) = rh0;
            *reinterpret_cast<uint4*>(b + TILE_H + (srow + 32) * KP + schunk * 8) = rh1;
            *reinterpret_cast<uint4*>(b + 2 * TILE_H + srow * KP + schunk * 8) = rl0;
            *reinterpret_cast<uint4*>(b + 2 * TILE_H + (srow + 32) * KP + schunk * 8) = rl1;
        }
        __syncthreads();
    }

    // ---- epilogue: rowsum(e) partials + partial O ----
    rs0 += __shfl_xor_sync(0xffffffffu, rs0, 1);
    rs0 += __shfl_xor_sync(0xffffffffu, rs0, 2);
    rs1 += __shfl_xor_sync(0xffffffffu, rs1, 1);
    rs1 += __shfl_xor_sync(0xffffffffu, rs1, 2);

    int rowa = qrow0 + m0 + r, rowb = rowa + 8;
    if (t == 0) {
        g_esum[blockIdx.y * NW + rowa] = rs0;
        g_esum[blockIdx.y * NW + rowb] = rs1;
    }
    float* part = g_part + blockIdx.y * NW * PW;
    #pragma unroll
    for (int nb = 0; nb < 8; nb++) {
        *reinterpret_cast<float2*>(&part[rowa * PW + nb * 8 + 2 * t]) =
            make_float2(oacc[nb][0], oacc[nb][1]);
        *reinterpret_cast<float2*>(&part[rowb * PW + nb * 8 + 2 * t]) =
            make_float2(oacc[nb][2], oacc[nb][3]);
    }
}

// ------------- kernel 3b: combine splits + colsumV, normalize -------------
__global__ __launch_bounds__(256) void combine_kernel() {
    int idx = blockIdx.x * 256 + threadIdx.x;   // NW*PW total
    int i = idx >> 6, j = idx & 63;
    float denom = 8192.f + g_esum[i] + g_esum[NW + i];
    float num = g_csv[j] + g_part[i * PW + j] + g_part[NW * PW + i * PW + j];
    g_head[i * PW + j] = num / denom;
}

// ------------- kernel 4: out = head @ W_sum  (fp32 FFMA) -------------
__global__ __launch_bounds__(256) void oproj_kernel(float* __restrict__ out) {
    __shared__ float hs[64][68];
    __shared__ float wss[64][68];

    int row0 = blockIdx.x * 64;
    int n0 = blockIdx.y * 64;
    int tid = threadIdx.x;

    #pragma unroll
    for (int i = 0; i < 4; i++) {
        int idx = tid + i * 256;
        int rr = idx >> 4, c4 = (idx & 15) * 4;
        *reinterpret_cast<float4*>(&hs[rr][c4]) =
            *reinterpret_cast<const float4*>(&g_head[(row0 + rr) * PW + c4]);
        *reinterpret_cast<float4*>(&wss[rr][c4]) =
            *reinterpret_cast<const float4*>(&g_wsum[rr * WW + n0 + c4]);
    }
    __syncthreads();

    int ty = tid >> 4, tx = tid & 15;
    float acc[4][4] = {};
    #pragma unroll
    for (int k = 0; k < 64; k++) {
        float a[4];
        #pragma unroll
        for (int i = 0; i < 4; i++) a[i] = hs[ty * 4 + i][k];
        float4 b = *reinterpret_cast<float4*>(&wss[k][tx * 4]);
        #pragma unroll
        for (int i = 0; i < 4; i++) {
            acc[i][0] += a[i] * b.x;
            acc[i][1] += a[i] * b.y;
            acc[i][2] += a[i] * b.z;
            acc[i][3] += a[i] * b.w;
        }
    }

    #pragma unroll
    for (int i = 0; i < 4; i++)
        #pragma unroll
        for (int j = 0; j < 4; j++)
            out[(row0 + ty * 4 + i) * WW + n0 + tx * 4 + j] = acc[i][j];
}

// ------------- launch -------------
extern "C" void kernel_launch(void* const* d_in, const int* in_sizes, int n_in,
                              void* d_out, int out_size) {
    const float* x  = (const float*)d_in[0];
    const float* wq = (const float*)d_in[1];
    const float* wk = (const float*)d_in[2];
    const float* wv = (const float*)d_in[3];
    const float* wo = (const float*)d_in[4];
    float* out = (float*)d_out;

    cudaFuncSetAttribute(attn_kernel, cudaFuncAttributeMaxDynamicSharedMemorySize,
                         SMEM_ATTN_BYTES);

    qkv_kernel<<<dim3(128, 3), 256>>>(x, wq, wk, wv);
    wsum_kernel<<<128, 256>>>(wo);
    colsumv_kernel<<<64, 256>>>();
    attn_kernel<<<dim3(64, 2), 256, SMEM_ATTN_BYTES>>>();
    combine_kernel<<<(NW * PW) / 256, 256>>>();
    oproj_kernel<<<dim3(128, 8), 256>>>(out);
}

// round 5
// speedup vs baseline: 1.9743x; 1.0698x over previous
#include <cuda_runtime.h>
#include <cuda_bf16.h>
#include <cstdint>

#define NW 8192
#define WW 512
#define PW 64
#define KP 72                 // smem tile pitch in bf16 elems
#define TILE_H (64 * KP)      // elems per 64x64 tile
#define NSPLIT 4
#define KVLEN (NW / NSPLIT)   // 2048

// ------------- device scratch (static, no allocation) -------------
__device__ __align__(16) __nv_bfloat16 g_qb[NW * PW];
__device__ __align__(16) __nv_bfloat16 g_kb[NW * PW];
__device__ __align__(16) __nv_bfloat16 g_vhiT[PW * NW];   // [out_col][kv_row]
__device__ __align__(16) __nv_bfloat16 g_vloT[PW * NW];   // colsum only
__device__ __align__(16) float g_part[NSPLIT * NW * PW];
__device__ float g_esum[NSPLIT * NW];
__device__ float g_csv[PW];
__device__ __align__(16) float g_head[NW * PW];
__device__ __align__(16) float g_wsum[PW * WW];

// ------------- helpers -------------
__device__ __forceinline__ unsigned short bfb(__nv_bfloat16 b) {
    return reinterpret_cast<unsigned short&>(b);
}

__device__ __forceinline__ void mma16(float* d, const uint32_t* a, uint32_t b0, uint32_t b1) {
    asm volatile("mma.sync.aligned.m16n8k16.row.col.f32.bf16.bf16.f32 "
                 "{%0,%1,%2,%3},{%4,%5,%6,%7},{%8,%9},{%0,%1,%2,%3};"
                 : "+f"(d[0]), "+f"(d[1]), "+f"(d[2]), "+f"(d[3])
                 : "r"(a[0]), "r"(a[1]), "r"(a[2]), "r"(a[3]), "r"(b0), "r"(b1));
}

__device__ __forceinline__ void ldsm4(uint32_t& r0, uint32_t& r1, uint32_t& r2, uint32_t& r3,
                                      uint32_t addr) {
    asm volatile("ldmatrix.sync.aligned.m8n8.x4.shared.b16 {%0,%1,%2,%3},[%4];"
                 : "=r"(r0), "=r"(r1), "=r"(r2), "=r"(r3) : "r"(addr));
}

__device__ __forceinline__ float ex2(float x) {
    float r; asm("ex2.approx.f32 %0,%1;" : "=f"(r) : "f"(x)); return r;
}

__device__ __forceinline__ uint32_t pk2(float lo, float hi) {
    uint32_t r; asm("cvt.rn.bf16x2.f32 %0,%1,%2;" : "=r"(r) : "f"(hi), "f"(lo)); return r;
}

// ------------- kernel 1: fused q/k/v = x @ w  (fp32 FFMA, bf16 outputs) -------------
// grid 256 blocks of 32 rows; x staged once, 3 weight tiles, 3 accumulator sets.
__global__ __launch_bounds__(256, 2) void qkv_kernel(const float* __restrict__ x,
                                                     const float* __restrict__ wq,
                                                     const float* __restrict__ wk,
                                                     const float* __restrict__ wv) {
    __shared__ float xs[32][36];
    __shared__ float ws[3][32][68];

    const float* wp[3] = {wq, wk, wv};
    int row0 = blockIdx.x * 32;
    int tid = threadIdx.x;
    int ty = tid >> 4, tx = tid & 15;

    float acc[3][2][4] = {};

    for (int kc = 0; kc < WW; kc += 32) {
        // stage x tile 32x32 (256 float4, 1 per thread)
        {
            int r = tid >> 3, c4 = (tid & 7) * 4;
            *reinterpret_cast<float4*>(&xs[r][c4]) =
                *reinterpret_cast<const float4*>(&x[(row0 + r) * WW + kc + c4]);
        }
        // stage 3 weight tiles 32x64 (512 float4 each, 2 per thread per tile)
        #pragma unroll
        for (int p = 0; p < 3; p++) {
            #pragma unroll
            for (int i = 0; i < 2; i++) {
                int idx = tid + i * 256;
                int r = idx >> 4, c4 = (idx & 15) * 4;
                *reinterpret_cast<float4*>(&ws[p][r][c4]) =
                    *reinterpret_cast<const float4*>(&wp[p][(kc + r) * PW + c4]);
            }
        }
        __syncthreads();

        #pragma unroll
        for (int k = 0; k < 32; k++) {
            float a0 = xs[ty * 2][k];
            float a1 = xs[ty * 2 + 1][k];
            #pragma unroll
            for (int p = 0; p < 3; p++) {
                float4 b = *reinterpret_cast<float4*>(&ws[p][k][tx * 4]);
                acc[p][0][0] += a0 * b.x; acc[p][0][1] += a0 * b.y;
                acc[p][0][2] += a0 * b.z; acc[p][0][3] += a0 * b.w;
                acc[p][1][0] += a1 * b.x; acc[p][1][1] += a1 * b.y;
                acc[p][1][2] += a1 * b.z; acc[p][1][3] += a1 * b.w;
            }
        }
        __syncthreads();
    }

    // q, k -> bf16 row-major
    #pragma unroll
    for (int p = 0; p < 2; p++) {
        __nv_bfloat16* out = (p == 0) ? g_qb : g_kb;
        #pragma unroll
        for (int i = 0; i < 2; i++) {
            ushort4 u;
            u.x = bfb(__float2bfloat16(acc[p][i][0]));
            u.y = bfb(__float2bfloat16(acc[p][i][1]));
            u.z = bfb(__float2bfloat16(acc[p][i][2]));
            u.w = bfb(__float2bfloat16(acc[p][i][3]));
            *reinterpret_cast<ushort4*>(&out[(row0 + ty * 2 + i) * PW + tx * 4]) = u;
        }
    }
    // v -> hi/lo bf16, transposed [out_col][kv_row]
    #pragma unroll
    for (int j = 0; j < 4; j++) {
        ushort2 uh, ul;
        unsigned short* ph = &uh.x;
        unsigned short* pl = &ul.x;
        #pragma unroll
        for (int i = 0; i < 2; i++) {
            float a = acc[2][i][j];
            __nv_bfloat16 h = __float2bfloat16(a);
            __nv_bfloat16 l = __float2bfloat16(a - __bfloat162float(h));
            ph[i] = bfb(h);
            pl[i] = bfb(l);
        }
        int off = (tx * 4 + j) * NW + row0 + ty * 2;
        *reinterpret_cast<ushort2*>(&g_vhiT[off]) = uh;
        *reinterpret_cast<ushort2*>(&g_vloT[off]) = ul;
    }
}

// ------------- kernel 2: W_sum[i][j] = sum_h w_o[h*64+i][j] -------------
__global__ __launch_bounds__(256) void wsum_kernel(const float* __restrict__ wo) {
    int idx = blockIdx.x * 256 + threadIdx.x;
    int i = idx >> 9, j = idx & 511;
    float s = 0.f;
    #pragma unroll
    for (int h = 0; h < 8; h++) s += wo[(h * 64 + i) * WW + j];
    g_wsum[i * WW + j] = s;
}

// ------------- kernel 2b: colsumV[j] = sum_i v[i][j] (hi+lo, exact) -------------
__global__ __launch_bounds__(256) void colsumv_kernel() {
    int j = blockIdx.x;
    const __nv_bfloat16* H = g_vhiT + j * NW;
    const __nv_bfloat16* L = g_vloT + j * NW;
    float s = 0.f;
    for (int i = threadIdx.x; i < NW; i += 256)
        s += __bfloat162float(H[i]) + __bfloat162float(L[i]);
    #pragma unroll
    for (int o = 16; o; o >>= 1) s += __shfl_xor_sync(0xffffffffu, s, o);
    __shared__ float red[8];
    if ((threadIdx.x & 31) == 0) red[threadIdx.x >> 5] = s;
    __syncthreads();
    if (threadIdx.x == 0) {
        float t = 0.f;
        #pragma unroll
        for (int w = 0; w < 8; w++) t += red[w];
        g_csv[j] = t;
    }
}

// ------------- kernel 3: fused attention (bf16 mma, p = 1+e, V_hi only) -------------
// grid (64, NSPLIT): 64 row-blocks of 128 rows, NSPLIT KV-splits. 8 warps.
#define SMEM_ATTN_BYTES (2 * 2 * TILE_H * 2)

__global__ __launch_bounds__(256, 2) void attn_kernel() {
    extern __shared__ __align__(16) uint16_t sm[];

    const int tid = threadIdx.x, warp = tid >> 5, lane = tid & 31;
    const int r = lane >> 2, t = lane & 3;
    const int m0 = warp * 16;
    const int qrow0 = blockIdx.x * 128;
    const int kvbase = blockIdx.y * KVLEN;

    // Q fragments resident in registers
    uint32_t aq[4][4];
    {
        const uint32_t* qb32 = reinterpret_cast<const uint32_t*>(g_qb);
        int ba = (qrow0 + m0 + r) * 32, bb = (qrow0 + m0 + r + 8) * 32;
        #pragma unroll
        for (int ks = 0; ks < 4; ks++) {
            aq[ks][0] = qb32[ba + ks * 8 + t];
            aq[ks][1] = qb32[bb + ks * 8 + t];
            aq[ks][2] = qb32[ba + ks * 8 + t + 4];
            aq[ks][3] = qb32[bb + ks * 8 + t + 4];
        }
    }

    const int srow = tid >> 3, schunk = tid & 7;
    const uint4* kb4 = reinterpret_cast<const uint4*>(g_kb);
    const uint4* vh4 = reinterpret_cast<const uint4*>(g_vhiT);

    const uint32_t smb = (uint32_t)__cvta_generic_to_shared(sm);
    const int nbase = ((lane >> 4) << 3) + (lane & 7);
    const int koff = ((lane >> 3) & 1) * 8;

    uint4 rk0, rk1, rh0, rh1;

    // prologue: tile 0 -> buffer 0
    {
        int kr0 = kvbase;
        rk0 = kb4[(kr0 + srow) * 8 + schunk];
        rk1 = kb4[(kr0 + srow + 32) * 8 + schunk];
        rh0 = vh4[srow * (NW / 8) + (kr0 >> 3) + schunk];
        rh1 = vh4[(srow + 32) * (NW / 8) + (kr0 >> 3) + schunk];
        uint16_t* b = sm;
        *reinterpret_cast<uint4*>(b + srow * KP + schunk * 8) = rk0;
        *reinterpret_cast<uint4*>(b + (srow + 32) * KP + schunk * 8) = rk1;
        *reinterpret_cast<uint4*>(b + TILE_H + srow * KP + schunk * 8) = rh0;
        *reinterpret_cast<uint4*>(b + TILE_H + (srow + 32) * KP + schunk * 8) = rh1;
    }
    __syncthreads();

    float oacc[8][4] = {};
    float rs0 = 0.f, rs1 = 0.f;
    const float cexp = 0.18033688f;   // (1/8) * log2(e)
    const int NITER = KVLEN / 64;

    for (int kb = 0; kb < NITER; kb++) {
        if (kb < NITER - 1) {
            int kr0 = kvbase + (kb + 1) * 64;
            rk0 = kb4[(kr0 + srow) * 8 + schunk];
            rk1 = kb4[(kr0 + srow + 32) * 8 + schunk];
            rh0 = vh4[srow * (NW / 8) + (kr0 >> 3) + schunk];
            rh1 = vh4[(srow + 32) * (NW / 8) + (kr0 >> 3) + schunk];
        }

        uint32_t cb = smb + (uint32_t)((kb & 1) * 2 * TILE_H * 2);

        // ---- S = Q K^T  (warp: 16 x 64) ----
        float sacc[8][4] = {};
        #pragma unroll
        for (int ks = 0; ks < 4; ks++) {
            #pragma unroll
            for (int jp = 0; jp < 4; jp++) {
                uint32_t b0, b1, b2, b3;
                ldsm4(b0, b1, b2, b3, cb + 2u * ((jp * 16 + nbase) * KP + ks * 16 + koff));
                mma16(sacc[2 * jp], aq[ks], b0, b1);
                mma16(sacc[2 * jp + 1], aq[ks], b2, b3);
            }
        }

        // ---- e = exp(S/8) - 1 -> PV A-fragments ----
        uint32_t ea[4][4];
        #pragma unroll
        for (int ks = 0; ks < 4; ks++) {
            float e00 = ex2(sacc[2 * ks][0] * cexp) - 1.f;
            float e01 = ex2(sacc[2 * ks][1] * cexp) - 1.f;
            float e02 = ex2(sacc[2 * ks][2] * cexp) - 1.f;
            float e03 = ex2(sacc[2 * ks][3] * cexp) - 1.f;
            float e10 = ex2(sacc[2 * ks + 1][0] * cexp) - 1.f;
            float e11 = ex2(sacc[2 * ks + 1][1] * cexp) - 1.f;
            float e12 = ex2(sacc[2 * ks + 1][2] * cexp) - 1.f;
            float e13 = ex2(sacc[2 * ks + 1][3] * cexp) - 1.f;
            rs0 += e00 + e01 + e10 + e11;
            rs1 += e02 + e03 + e12 + e13;
            ea[ks][0] = pk2(e00, e01);
            ea[ks][1] = pk2(e02, e03);
            ea[ks][2] = pk2(e10, e11);
            ea[ks][3] = pk2(e12, e13);
        }

        // ---- O += e * V_hi  (warp: 16 x 64) ----
        uint32_t hb = cb + 2u * TILE_H;
        #pragma unroll
        for (int ks = 0; ks < 4; ks++) {
            #pragma unroll
            for (int jp = 0; jp < 4; jp++) {
                uint32_t b0, b1, b2, b3;
                ldsm4(b0, b1, b2, b3, hb + 2u * ((jp * 16 + nbase) * KP + ks * 16 + koff));
                mma16(oacc[2 * jp], ea[ks], b0, b1);
                mma16(oacc[2 * jp + 1], ea[ks], b2, b3);
            }
        }

        if (kb < NITER - 1) {
            uint16_t* b = sm + ((kb + 1) & 1) * 2 * TILE_H;
            *reinterpret_cast<uint4*>(b + srow * KP + schunk * 8) = rk0;
            *reinterpret_cast<uint4*>(b + (srow + 32) * KP + schunk * 8) = rk1;
            *reinterpret_cast<uint4*>(b + TILE_H + srow * KP + schunk * 8) = rh0;
            *reinterpret_cast<uint4*>(b + TILE_H + (srow + 32) * KP + schunk * 8) = rh1;
        }
        __syncthreads();
    }

    // ---- epilogue ----
    rs0 += __shfl_xor_sync(0xffffffffu, rs0, 1);
    rs0 += __shfl_xor_sync(0xffffffffu, rs0, 2);
    rs1 += __shfl_xor_sync(0xffffffffu, rs1, 1);
    rs1 += __shfl_xor_sync(0xffffffffu, rs1, 2);

    int rowa = qrow0 + m0 + r, rowb = rowa + 8;
    if (t == 0) {
        g_esum[blockIdx.y * NW + rowa] = rs0;
        g_esum[blockIdx.y * NW + rowb] = rs1;
    }
    float* part = g_part + blockIdx.y * NW * PW;
    #pragma unroll
    for (int nb = 0; nb < 8; nb++) {
        *reinterpret_cast<float2*>(&part[rowa * PW + nb * 8 + 2 * t]) =
            make_float2(oacc[nb][0], oacc[nb][1]);
        *reinterpret_cast<float2*>(&part[rowb * PW + nb * 8 + 2 * t]) =
            make_float2(oacc[nb][2], oacc[nb][3]);
    }
}

// ------------- kernel 3b: combine splits + colsumV, normalize -------------
__global__ __launch_bounds__(256) void combine_kernel() {
    int idx = blockIdx.x * 256 + threadIdx.x;
    int i = idx >> 6, j = idx & 63;
    float denom = 8192.f;
    float num = g_csv[j];
    #pragma unroll
    for (int s = 0; s < NSPLIT; s++) {
        denom += g_esum[s * NW + i];
        num += g_part[s * NW * PW + i * PW + j];
    }
    g_head[i * PW + j] = num / denom;
}

// ------------- kernel 4: out = head @ W_sum  (fp32 FFMA, 128x64 blocks) -------------
__global__ __launch_bounds__(256) void oproj_kernel(float* __restrict__ out) {
    __shared__ float hs[128][68];
    __shared__ float wss[64][68];

    int row0 = blockIdx.x * 128;
    int n0 = blockIdx.y * 64;
    int tid = threadIdx.x;

    #pragma unroll
    for (int i = 0; i < 8; i++) {
        int idx = tid + i * 256;
        int rr = idx >> 4, c4 = (idx & 15) * 4;
        *reinterpret_cast<float4*>(&hs[rr][c4]) =
            *reinterpret_cast<const float4*>(&g_head[(row0 + rr) * PW + c4]);
    }
    #pragma unroll
    for (int i = 0; i < 4; i++) {
        int idx = tid + i * 256;
        int rr = idx >> 4, c4 = (idx & 15) * 4;
        *reinterpret_cast<float4*>(&wss[rr][c4]) =
            *reinterpret_cast<const float4*>(&g_wsum[rr * WW + n0 + c4]);
    }
    __syncthreads();

    int ty = tid >> 4, tx = tid & 15;
    float acc[8][4] = {};
    #pragma unroll
    for (int k = 0; k < 64; k++) {
        float a[8];
        #pragma unroll
        for (int i = 0; i < 8; i++) a[i] = hs[ty * 8 + i][k];
        float4 b = *reinterpret_cast<float4*>(&wss[k][tx * 4]);
        #pragma unroll
        for (int i = 0; i < 8; i++) {
            acc[i][0] += a[i] * b.x;
            acc[i][1] += a[i] * b.y;
            acc[i][2] += a[i] * b.z;
            acc[i][3] += a[i] * b.w;
        }
    }

    #pragma unroll
    for (int i = 0; i < 8; i++)
        #pragma unroll
        for (int j = 0; j < 4; j++)
            out[(row0 + ty * 8 + i) * WW + n0 + tx * 4 + j] = acc[i][j];
}

// ------------- launch -------------
extern "C" void kernel_launch(void* const* d_in, const int* in_sizes, int n_in,
                              void* d_out, int out_size) {
    const float* x  = (const float*)d_in[0];
    const float* wq = (const float*)d_in[1];
    const float* wk = (const float*)d_in[2];
    const float* wv = (const float*)d_in[3];
    const float* wo = (const float*)d_in[4];
    float* out = (float*)d_out;

    cudaFuncSetAttribute(attn_kernel, cudaFuncAttributeMaxDynamicSharedMemorySize,
                         SMEM_ATTN_BYTES);

    qkv_kernel<<<256, 256>>>(x, wq, wk, wv);
    wsum_kernel<<<128, 256>>>(wo);
    colsumv_kernel<<<64, 256>>>();
    attn_kernel<<<dim3(64, NSPLIT), 256, SMEM_ATTN_BYTES>>>();
    combine_kernel<<<(NW * PW) / 256, 256>>>();
    oproj_kernel<<<dim3(64, 8), 256>>>(out);
}

// round 6
// speedup vs baseline: 2.4690x; 1.2506x over previous
#include <cuda_runtime.h>
#include <cuda_bf16.h>
#include <cstdint>

#define NW 8192
#define WW 512
#define PW 64
#define KP 72                 // attn smem tile pitch (bf16 elems)
#define TILE_H (64 * KP)
#define NSPLIT 4
#define KVLEN (NW / NSPLIT)   // 2048
#define CEXP 0.18033688f      // (1/8) * log2(e)

// ------------- device scratch (static, no allocation) -------------
__device__ __align__(16) __nv_bfloat16 g_qb[NW * PW];     // pre-scaled by CEXP
__device__ __align__(16) __nv_bfloat16 g_kb[NW * PW];
__device__ __align__(16) __nv_bfloat16 g_vhiT[PW * NW];   // [out_col][kv_row]
__device__ __align__(16) __nv_bfloat16 g_vloT[PW * NW];   // colsum only
__device__ __align__(16) float g_part[NSPLIT * NW * PW];
__device__ float g_esum[NSPLIT * NW];
__device__ float g_csv[PW];
__device__ __align__(16) float g_wsum[PW * WW];

// ------------- helpers -------------
__device__ __forceinline__ unsigned short bfb(__nv_bfloat16 b) {
    return reinterpret_cast<unsigned short&>(b);
}

__device__ __forceinline__ void mma16(float* d, const uint32_t* a, uint32_t b0, uint32_t b1) {
    asm volatile("mma.sync.aligned.m16n8k16.row.col.f32.bf16.bf16.f32 "
                 "{%0,%1,%2,%3},{%4,%5,%6,%7},{%8,%9},{%0,%1,%2,%3};"
                 : "+f"(d[0]), "+f"(d[1]), "+f"(d[2]), "+f"(d[3])
                 : "r"(a[0]), "r"(a[1]), "r"(a[2]), "r"(a[3]), "r"(b0), "r"(b1));
}

__device__ __forceinline__ void ldsm4(uint32_t& r0, uint32_t& r1, uint32_t& r2, uint32_t& r3,
                                      uint32_t addr) {
    asm volatile("ldmatrix.sync.aligned.m8n8.x4.shared.b16 {%0,%1,%2,%3},[%4];"
                 : "=r"(r0), "=r"(r1), "=r"(r2), "=r"(r3) : "r"(addr));
}

__device__ __forceinline__ float ex2(float x) {
    float r; asm("ex2.approx.f32 %0,%1;" : "=f"(r) : "f"(x)); return r;
}

__device__ __forceinline__ uint32_t pk2(float lo, float hi) {
    uint32_t r; asm("cvt.rn.bf16x2.f32 %0,%1,%2;" : "=r"(r) : "f"(hi), "f"(lo)); return r;
}

// e = exp2(s) - 1 for two sacc fragments -> one PV A-chunk (R4-verified mapping)
__device__ __forceinline__ void softmax2(const float* sA, const float* sB,
                                         uint32_t* ea, float& rs0, float& rs1) {
    float e00 = ex2(sA[0]) - 1.f, e01 = ex2(sA[1]) - 1.f;
    float e02 = ex2(sA[2]) - 1.f, e03 = ex2(sA[3]) - 1.f;
    float e10 = ex2(sB[0]) - 1.f, e11 = ex2(sB[1]) - 1.f;
    float e12 = ex2(sB[2]) - 1.f, e13 = ex2(sB[3]) - 1.f;
    rs0 += e00 + e01 + e10 + e11;
    rs1 += e02 + e03 + e12 + e13;
    ea[0] = pk2(e00, e01);
    ea[1] = pk2(e02, e03);
    ea[2] = pk2(e10, e11);
    ea[3] = pk2(e12, e13);
}

// ------------- kernel 1: q,k = x @ [w_q|w_k]  (bf16 tensor GEMM) -------------
// grid 128 x 64-row blocks; 8 warps: warps 0-3 -> q cols, 4-7 -> k cols.
#define XP 40
#define BP 40
__global__ __launch_bounds__(256, 2) void qk_kernel(const float* __restrict__ x,
                                                    const float* __restrict__ wq,
                                                    const float* __restrict__ wk) {
    __shared__ __align__(16) uint16_t xs[64 * XP];    // x tile bf16 [64][32]
    __shared__ __align__(16) uint16_t bs[128 * BP];   // [n=128][k=32], n<64=q, n>=64=k

    const int tid = threadIdx.x, warp = tid >> 5, lane = tid & 31;
    const int r = lane >> 2, t = lane & 3;
    const int wm = warp & 3, wn = warp >> 2;
    const int row0 = blockIdx.x * 64;

    const uint32_t xb = (uint32_t)__cvta_generic_to_shared(xs);
    const uint32_t bb = (uint32_t)__cvta_generic_to_shared(bs);
    const int arow = lane & 15, ahalf = (lane >> 4) * 8;
    const int nbase = ((lane >> 4) << 3) + (lane & 7);
    const int koff = ((lane >> 3) & 1) * 8;

    float acc[8][4] = {};

    for (int kc = 0; kc < WW; kc += 32) {
        // stage x tile 64x32 -> bf16 (512 float4 loads)
        #pragma unroll
        for (int i = 0; i < 2; i++) {
            int idx = tid + i * 256;
            int rr = idx >> 3, c4 = (idx & 7) * 4;
            float4 v = *reinterpret_cast<const float4*>(&x[(row0 + rr) * WW + kc + c4]);
            ushort4 u;
            u.x = bfb(__float2bfloat16(v.x));
            u.y = bfb(__float2bfloat16(v.y));
            u.z = bfb(__float2bfloat16(v.z));
            u.w = bfb(__float2bfloat16(v.w));
            *reinterpret_cast<ushort4*>(&xs[rr * XP + c4]) = u;
        }
        // stage wq and wk 32x64 -> bs transposed [n][k]
        {
            int rr = tid >> 3, n4 = (tid & 7) * 8;   // 256 thr cover 32 rows x 8 n4-chunks
            float4 a = *reinterpret_cast<const float4*>(&wq[(kc + rr) * PW + n4]);
            float4 b = *reinterpret_cast<const float4*>(&wq[(kc + rr) * PW + n4 + 4]);
            bs[(n4 + 0) * BP + rr] = bfb(__float2bfloat16(a.x));
            bs[(n4 + 1) * BP + rr] = bfb(__float2bfloat16(a.y));
            bs[(n4 + 2) * BP + rr] = bfb(__float2bfloat16(a.z));
            bs[(n4 + 3) * BP + rr] = bfb(__float2bfloat16(a.w));
            bs[(n4 + 4) * BP + rr] = bfb(__float2bfloat16(b.x));
            bs[(n4 + 5) * BP + rr] = bfb(__float2bfloat16(b.y));
            bs[(n4 + 6) * BP + rr] = bfb(__float2bfloat16(b.z));
            bs[(n4 + 7) * BP + rr] = bfb(__float2bfloat16(b.w));
            float4 c = *reinterpret_cast<const float4*>(&wk[(kc + rr) * PW + n4]);
            float4 d = *reinterpret_cast<const float4*>(&wk[(kc + rr) * PW + n4 + 4]);
            bs[(64 + n4 + 0) * BP + rr] = bfb(__float2bfloat16(c.x));
            bs[(64 + n4 + 1) * BP + rr] = bfb(__float2bfloat16(c.y));
            bs[(64 + n4 + 2) * BP + rr] = bfb(__float2bfloat16(c.z));
            bs[(64 + n4 + 3) * BP + rr] = bfb(__float2bfloat16(c.w));
            bs[(64 + n4 + 4) * BP + rr] = bfb(__float2bfloat16(d.x));
            bs[(64 + n4 + 5) * BP + rr] = bfb(__float2bfloat16(d.y));
            bs[(64 + n4 + 6) * BP + rr] = bfb(__float2bfloat16(d.z));
            bs[(64 + n4 + 7) * BP + rr] = bfb(__float2bfloat16(d.w));
        }
        __syncthreads();

        #pragma unroll
        for (int ks = 0; ks < 2; ks++) {
            uint32_t a[4];
            ldsm4(a[0], a[1], a[2], a[3],
                  xb + 2u * ((wm * 16 + arow) * XP + ks * 16 + ahalf));
            #pragma unroll
            for (int jp = 0; jp < 4; jp++) {
                uint32_t b0, b1, b2, b3;
                ldsm4(b0, b1, b2, b3,
                      bb + 2u * ((wn * 64 + jp * 16 + nbase) * BP + ks * 16 + koff));
                mma16(acc[2 * jp], a, b0, b1);
                mma16(acc[2 * jp + 1], a, b2, b3);
            }
        }
        __syncthreads();
    }

    // epilogue: q gets pre-scaled by CEXP
    float fac = (wn == 0) ? CEXP : 1.0f;
    __nv_bfloat16* outp = (wn == 0) ? g_qb : g_kb;
    int rowa = row0 + wm * 16 + r;
    #pragma unroll
    for (int jp = 0; jp < 4; jp++) {
        #pragma unroll
        for (int h = 0; h < 2; h++) {
            const float* c = acc[2 * jp + h];
            int col = jp * 16 + h * 8 + 2 * t;
            ushort2 ua, ub;
            ua.x = bfb(__float2bfloat16(c[0] * fac));
            ua.y = bfb(__float2bfloat16(c[1] * fac));
            ub.x = bfb(__float2bfloat16(c[2] * fac));
            ub.y = bfb(__float2bfloat16(c[3] * fac));
            *reinterpret_cast<ushort2*>(&outp[rowa * PW + col]) = ua;
            *reinterpret_cast<ushort2*>(&outp[(rowa + 8) * PW + col]) = ub;
        }
    }
}

// ------------- kernel 1b: v = x @ w_v  (fp32 FFMA, hi/lo bf16 transposed out) ----
__global__ __launch_bounds__(256, 2) void v_kernel(const float* __restrict__ x,
                                                   const float* __restrict__ wv) {
    __shared__ float xs[64][36];
    __shared__ float ws[32][68];

    int row0 = blockIdx.x * 64;
    int tid = threadIdx.x;
    int ty = tid >> 4, tx = tid & 15;

    float acc[4][4] = {};

    for (int kc = 0; kc < WW; kc += 32) {
        #pragma unroll
        for (int i = 0; i < 2; i++) {
            int idx = tid + i * 256;
            int r = idx >> 3, c4 = (idx & 7) * 4;
            *reinterpret_cast<float4*>(&xs[r][c4]) =
                *reinterpret_cast<const float4*>(&x[(row0 + r) * WW + kc + c4]);
        }
        #pragma unroll
        for (int i = 0; i < 2; i++) {
            int idx = tid + i * 256;
            int r = idx >> 4, c4 = (idx & 15) * 4;
            *reinterpret_cast<float4*>(&ws[r][c4]) =
                *reinterpret_cast<const float4*>(&wv[(kc + r) * PW + c4]);
        }
        __syncthreads();

        #pragma unroll
        for (int k = 0; k < 32; k++) {
            float a[4];
            #pragma unroll
            for (int i = 0; i < 4; i++) a[i] = xs[ty * 4 + i][k];
            float4 b = *reinterpret_cast<float4*>(&ws[k][tx * 4]);
            #pragma unroll
            for (int i = 0; i < 4; i++) {
                acc[i][0] += a[i] * b.x;
                acc[i][1] += a[i] * b.y;
                acc[i][2] += a[i] * b.z;
                acc[i][3] += a[i] * b.w;
            }
        }
        __syncthreads();
    }

    #pragma unroll
    for (int j = 0; j < 4; j++) {
        ushort4 uh, ul;
        unsigned short* ph = &uh.x;
        unsigned short* pl = &ul.x;
        #pragma unroll
        for (int i = 0; i < 4; i++) {
            float a = acc[i][j];
            __nv_bfloat16 h = __float2bfloat16(a);
            __nv_bfloat16 l = __float2bfloat16(a - __bfloat162float(h));
            ph[i] = bfb(h);
            pl[i] = bfb(l);
        }
        int off = (tx * 4 + j) * NW + row0 + ty * 4;
        *reinterpret_cast<ushort4*>(&g_vhiT[off]) = uh;
        *reinterpret_cast<ushort4*>(&g_vloT[off]) = ul;
    }
}

// ------------- kernel 2: prep = wsum (blocks 0-127) + colsumV (blocks 128-191) ---
__global__ __launch_bounds__(256) void prep_kernel(const float* __restrict__ wo) {
    if (blockIdx.x < 128) {
        int idx = blockIdx.x * 256 + threadIdx.x;
        int i = idx >> 9, j = idx & 511;
        float s = 0.f;
        #pragma unroll
        for (int h = 0; h < 8; h++) s += wo[(h * 64 + i) * WW + j];
        g_wsum[i * WW + j] = s;
    } else {
        int j = blockIdx.x - 128;
        const __nv_bfloat16* H = g_vhiT + j * NW;
        const __nv_bfloat16* L = g_vloT + j * NW;
        float s = 0.f;
        for (int i = threadIdx.x; i < NW; i += 256)
            s += __bfloat162float(H[i]) + __bfloat162float(L[i]);
        #pragma unroll
        for (int o = 16; o; o >>= 1) s += __shfl_xor_sync(0xffffffffu, s, o);
        __shared__ float red[8];
        if ((threadIdx.x & 31) == 0) red[threadIdx.x >> 5] = s;
        __syncthreads();
        if (threadIdx.x == 0) {
            float t = 0.f;
            #pragma unroll
            for (int w = 0; w < 8; w++) t += red[w];
            g_csv[j] = t;
        }
    }
}

// ------------- kernel 3: fused attention (sub-block pipelined) -------------
#define SMEM_ATTN_BYTES (2 * 2 * TILE_H * 2)

__global__ __launch_bounds__(256, 2) void attn_kernel() {
    extern __shared__ __align__(16) uint16_t sm[];

    const int tid = threadIdx.x, warp = tid >> 5, lane = tid & 31;
    const int r = lane >> 2, t = lane & 3;
    const int m0 = warp * 16;
    const int qrow0 = blockIdx.x * 128;
    const int kvbase = blockIdx.y * KVLEN;

    // Q fragments (pre-scaled by CEXP in qk_kernel)
    uint32_t aq[4][4];
    {
        const uint32_t* qb32 = reinterpret_cast<const uint32_t*>(g_qb);
        int ba = (qrow0 + m0 + r) * 32, bb = (qrow0 + m0 + r + 8) * 32;
        #pragma unroll
        for (int ks = 0; ks < 4; ks++) {
            aq[ks][0] = qb32[ba + ks * 8 + t];
            aq[ks][1] = qb32[bb + ks * 8 + t];
            aq[ks][2] = qb32[ba + ks * 8 + t + 4];
            aq[ks][3] = qb32[bb + ks * 8 + t + 4];
        }
    }

    const int srow = tid >> 3, schunk = tid & 7;
    const uint4* kb4 = reinterpret_cast<const uint4*>(g_kb);
    const uint4* vh4 = reinterpret_cast<const uint4*>(g_vhiT);

    const uint32_t smb = (uint32_t)__cvta_generic_to_shared(sm);
    const int nbase = ((lane >> 4) << 3) + (lane & 7);
    const int koff = ((lane >> 3) & 1) * 8;
    const uint32_t fragoff = 2u * (nbase * KP + koff);

    uint4 rk0, rk1, rh0, rh1;

    {   // prologue: tile 0 -> buffer 0
        int kr0 = kvbase;
        rk0 = kb4[(kr0 + srow) * 8 + schunk];
        rk1 = kb4[(kr0 + srow + 32) * 8 + schunk];
        rh0 = vh4[srow * (NW / 8) + (kr0 >> 3) + schunk];
        rh1 = vh4[(srow + 32) * (NW / 8) + (kr0 >> 3) + schunk];
        uint16_t* b = sm;
        *reinterpret_cast<uint4*>(b + srow * KP + schunk * 8) = rk0;
        *reinterpret_cast<uint4*>(b + (srow + 32) * KP + schunk * 8) = rk1;
        *reinterpret_cast<uint4*>(b + TILE_H + srow * KP + schunk * 8) = rh0;
        *reinterpret_cast<uint4*>(b + TILE_H + (srow + 32) * KP + schunk * 8) = rh1;
    }
    __syncthreads();

    float oacc[8][4] = {};
    float rs0 = 0.f, rs1 = 0.f;
    const int NITER = KVLEN / 64;

    for (int kb = 0; kb < NITER; kb++) {
        if (kb < NITER - 1) {
            int kr0 = kvbase + (kb + 1) * 64;
            rk0 = kb4[(kr0 + srow) * 8 + schunk];
            rk1 = kb4[(kr0 + srow + 32) * 8 + schunk];
            rh0 = vh4[srow * (NW / 8) + (kr0 >> 3) + schunk];
            rh1 = vh4[(srow + 32) * (NW / 8) + (kr0 >> 3) + schunk];
        }

        uint32_t cb = smb + (uint32_t)((kb & 1) * 2 * TILE_H * 2);
        uint32_t ab = cb + fragoff;               // K tile frag base
        uint32_t vb = ab + 2u * TILE_H;           // V tile frag base

        // ---- S sub0: KV cols 0-31 ----
        float s0[4][4] = {};
        #pragma unroll
        for (int ks = 0; ks < 4; ks++) {
            #pragma unroll
            for (int jp = 0; jp < 2; jp++) {
                uint32_t b0, b1, b2, b3;
                ldsm4(b0, b1, b2, b3, ab + 2u * (jp * 16 * KP + ks * 16));
                mma16(s0[2 * jp], aq[ks], b0, b1);
                mma16(s0[2 * jp + 1], aq[ks], b2, b3);
            }
        }
        // ---- S sub1: KV cols 32-63 ----
        float s1[4][4] = {};
        #pragma unroll
        for (int ks = 0; ks < 4; ks++) {
            #pragma unroll
            for (int jp = 2; jp < 4; jp++) {
                uint32_t b0, b1, b2, b3;
                ldsm4(b0, b1, b2, b3, ab + 2u * (jp * 16 * KP + ks * 16));
                mma16(s1[2 * (jp - 2)], aq[ks], b0, b1);
                mma16(s1[2 * (jp - 2) + 1], aq[ks], b2, b3);
            }
        }
        // ---- e0 (overlaps with S sub1 tensor drain) ----
        uint32_t ea0[2][4];
        softmax2(s0[0], s0[1], ea0[0], rs0, rs1);
        softmax2(s0[2], s0[3], ea0[1], rs0, rs1);
        // ---- PV sub0: KV rows 0-31 (k-chunks 0,1) ----
        #pragma unroll
        for (int cs = 0; cs < 2; cs++) {
            #pragma unroll
            for (int jp = 0; jp < 4; jp++) {
                uint32_t b0, b1, b2, b3;
                ldsm4(b0, b1, b2, b3, vb + 2u * (jp * 16 * KP + cs * 16));
                mma16(oacc[2 * jp], ea0[cs], b0, b1);
                mma16(oacc[2 * jp + 1], ea0[cs], b2, b3);
            }
        }
        // ---- e1 (overlaps with PV sub0 tensor drain) ----
        uint32_t ea1[2][4];
        softmax2(s1[0], s1[1], ea1[0], rs0, rs1);
        softmax2(s1[2], s1[3], ea1[1], rs0, rs1);
        // ---- PV sub1: KV rows 32-63 (k-chunks 2,3) ----
        #pragma unroll
        for (int cs = 0; cs < 2; cs++) {
            #pragma unroll
            for (int jp = 0; jp < 4; jp++) {
                uint32_t b0, b1, b2, b3;
                ldsm4(b0, b1, b2, b3, vb + 2u * (jp * 16 * KP + (2 + cs) * 16));
                mma16(oacc[2 * jp], ea1[cs], b0, b1);
                mma16(oacc[2 * jp + 1], ea1[cs], b2, b3);
            }
        }

        if (kb < NITER - 1) {
            uint16_t* b = sm + ((kb + 1) & 1) * 2 * TILE_H;
            *reinterpret_cast<uint4*>(b + srow * KP + schunk * 8) = rk0;
            *reinterpret_cast<uint4*>(b + (srow + 32) * KP + schunk * 8) = rk1;
            *reinterpret_cast<uint4*>(b + TILE_H + srow * KP + schunk * 8) = rh0;
            *reinterpret_cast<uint4*>(b + TILE_H + (srow + 32) * KP + schunk * 8) = rh1;
        }
        __syncthreads();
    }

    // ---- epilogue ----
    rs0 += __shfl_xor_sync(0xffffffffu, rs0, 1);
    rs0 += __shfl_xor_sync(0xffffffffu, rs0, 2);
    rs1 += __shfl_xor_sync(0xffffffffu, rs1, 1);
    rs1 += __shfl_xor_sync(0xffffffffu, rs1, 2);

    int rowa = qrow0 + m0 + r, rowb = rowa + 8;
    if (t == 0) {
        g_esum[blockIdx.y * NW + rowa] = rs0;
        g_esum[blockIdx.y * NW + rowb] = rs1;
    }
    float* part = g_part + blockIdx.y * NW * PW;
    #pragma unroll
    for (int nb = 0; nb < 8; nb++) {
        *reinterpret_cast<float2*>(&part[rowa * PW + nb * 8 + 2 * t]) =
            make_float2(oacc[nb][0], oacc[nb][1]);
        *reinterpret_cast<float2*>(&part[rowb * PW + nb * 8 + 2 * t]) =
            make_float2(oacc[nb][2], oacc[nb][3]);
    }
}

// ------------- kernel 4: out = head @ W_sum with fused combine -------------
__global__ __launch_bounds__(256) void oproj_kernel(float* __restrict__ out) {
    __shared__ float hs[128][68];
    __shared__ float wss[64][68];
    __shared__ float rden[128];

    int row0 = blockIdx.x * 128;
    int n0 = blockIdx.y * 64;
    int tid = threadIdx.x;

    if (tid < 128) {
        int i = row0 + tid;
        float d = 8192.f;
        #pragma unroll
        for (int s = 0; s < NSPLIT; s++) d += g_esum[s * NW + i];
        rden[tid] = 1.0f / d;
    }
    __syncthreads();

    // stage head = (csv + sum parts) * rden  (fused combine)
    #pragma unroll
    for (int i = 0; i < 8; i++) {
        int idx = tid + i * 256;
        int rr = idx >> 4, c4 = (idx & 15) * 4;
        float4 s = *reinterpret_cast<const float4*>(&g_csv[c4]);
        #pragma unroll
        for (int sp = 0; sp < NSPLIT; sp++) {
            float4 p = *reinterpret_cast<const float4*>(
                &g_part[sp * NW * PW + (row0 + rr) * PW + c4]);
            s.x += p.x; s.y += p.y; s.z += p.z; s.w += p.w;
        }
        float rd = rden[rr];
        s.x *= rd; s.y *= rd; s.z *= rd; s.w *= rd;
        *reinterpret_cast<float4*>(&hs[rr][c4]) = s;
    }
    #pragma unroll
    for (int i = 0; i < 4; i++) {
        int idx = tid + i * 256;
        int rr = idx >> 4, c4 = (idx & 15) * 4;
        *reinterpret_cast<float4*>(&wss[rr][c4]) =
            *reinterpret_cast<const float4*>(&g_wsum[rr * WW + n0 + c4]);
    }
    __syncthreads();

    int ty = tid >> 4, tx = tid & 15;
    float acc[8][4] = {};
    #pragma unroll
    for (int k = 0; k < 64; k++) {
        float a[8];
        #pragma unroll
        for (int i = 0; i < 8; i++) a[i] = hs[ty * 8 + i][k];
        float4 b = *reinterpret_cast<float4*>(&wss[k][tx * 4]);
        #pragma unroll
        for (int i = 0; i < 8; i++) {
            acc[i][0] += a[i] * b.x;
            acc[i][1] += a[i] * b.y;
            acc[i][2] += a[i] * b.z;
            acc[i][3] += a[i] * b.w;
        }
    }

    #pragma unroll
    for (int i = 0; i < 8; i++)
        #pragma unroll
        for (int j = 0; j < 4; j++)
            out[(row0 + ty * 8 + i) * WW + n0 + tx * 4 + j] = acc[i][j];
}

// ------------- launch -------------
extern "C" void kernel_launch(void* const* d_in, const int* in_sizes, int n_in,
                              void* d_out, int out_size) {
    const float* x  = (const float*)d_in[0];
    const float* wq = (const float*)d_in[1];
    const float* wk = (const float*)d_in[2];
    const float* wv = (const float*)d_in[3];
    const float* wo = (const float*)d_in[4];
    float* out = (float*)d_out;

    cudaFuncSetAttribute(attn_kernel, cudaFuncAttributeMaxDynamicSharedMemorySize,
                         SMEM_ATTN_BYTES);

    qk_kernel<<<128, 256>>>(x, wq, wk);
    v_kernel<<<128, 256>>>(x, wv);
    prep_kernel<<<192, 256>>>(wo);
    attn_kernel<<<dim3(64, NSPLIT), 256, SMEM_ATTN_BYTES>>>();
    oproj_kernel<<<dim3(64, 8), 256>>>(out);
}